// round 4
// baseline (speedup 1.0000x reference)
#include <cuda_runtime.h>
#include <cuda_bf16.h>

#define B_ROWS 32768
#define FEAT_D 2048
#define NBLK   1024
#define RPB    (B_ROWS / NBLK)   // 32 rows per block

// Global scalar accumulators (no allocation allowed)
__device__ double g_X;      // sum_j s_j . c_j
__device__ double g_AX;     // sum_cols T * (c0+c1+c2)
__device__ double g_Q;      // sum ||feat||^2
__device__ int    g_cnt0, g_cnt1;
__device__ int    g_ticket;
__device__ int    g_stride; // 1 = int32 labels, 2 = int64 (read low word)

__global__ void init_k(const int* __restrict__ label32) {
    if (threadIdx.x == 0) {
        g_X = 0.0; g_AX = 0.0; g_Q = 0.0;
        g_cnt0 = 0; g_cnt1 = 0; g_ticket = 0;
        // int64 labels in {0,1,2}: odd int32 words all zero. For int32 labels
        // P(64 draws from {0,1,2} all land 0 at odd slots) ~ (1/3)^64 ~ 0.
        int nz = 0;
#pragma unroll
        for (int i = 0; i < 64; ++i) nz |= label32[2 * i + 1];
        g_stride = nz ? 1 : 2;
    }
}

__device__ __forceinline__ double blk_reduce(double v, double (*sred)[4], int slot,
                                             int tid) {
#pragma unroll
    for (int off = 16; off > 0; off >>= 1)
        v += __shfl_xor_sync(0xFFFFFFFFu, v, off);
    if ((tid & 31) == 0) sred[tid >> 5][slot] = v;
    __syncthreads();
    double r = 0.0;
    if (tid < 8) r = sred[tid][slot];
#pragma unroll
    for (int off = 4; off > 0; off >>= 1)
        r += __shfl_xor_sync(0xFFu, r, off);
    return r;  // valid in tid 0
}

// dot of one row-slice (two float4) against one center slice
#define DOT8(d, A, B, CA, CB)                                \
    {   d = A.x * CA.x;          d = fmaf(A.y, CA.y, d);     \
        d = fmaf(A.z, CA.z, d);  d = fmaf(A.w, CA.w, d);     \
        d = fmaf(B.x, CB.x, d);  d = fmaf(B.y, CB.y, d);     \
        d = fmaf(B.z, CB.z, d);  d = fmaf(B.w, CB.w, d); }

__global__ void __launch_bounds__(256, 4)
accum_k(const float* __restrict__ feat, const int* __restrict__ label32,
        const float* __restrict__ centers, float* __restrict__ out) {
    __shared__ int    s_lab[RPB];
    __shared__ double s_red[8][4];
    __shared__ int    s_last;

    const int tid = threadIdx.x;
    const int r0  = blockIdx.x * RPB;

    if (tid < RPB) s_lab[tid] = label32[(size_t)g_stride * (r0 + tid)];

    // Preload center slices for this thread's 8 columns (cached, all blocks reuse)
    const float4* c4 = reinterpret_cast<const float4*>(centers);
    const float4 C0a = c4[tid],        C0b = c4[tid + 256];
    const float4 C1a = c4[512 + tid],  C1b = c4[512 + tid + 256];
    const float4 C2a = c4[1024 + tid], C2b = c4[1024 + tid + 256];
    __syncthreads();

    float x = 0.0f, ax = 0.0f, q = 0.0f;

    const float4* fp = reinterpret_cast<const float4*>(feat)
                     + (size_t)r0 * (FEAT_D / 4) + tid;

#pragma unroll 4
    for (int i = 0; i < RPB; i += 2, fp += 2 * (FEAT_D / 4)) {
        // front-batch 4 independent 16B loads (2 rows)
        float4 a0 = __ldcs(fp);
        float4 b0 = __ldcs(fp + 256);
        float4 a1 = __ldcs(fp + 512);
        float4 b1 = __ldcs(fp + 768);

        {
            float d0, d1, d2, dq;
            DOT8(d0, a0, b0, C0a, C0b)
            DOT8(d1, a0, b0, C1a, C1b)
            DOT8(d2, a0, b0, C2a, C2b)
            DOT8(dq, a0, b0, a0,  b0)
            const int l = s_lab[i];
            x += (l == 0) ? d0 : ((l == 1) ? d1 : d2);
            ax += d0 + d1 + d2;
            q  += dq;
        }
        {
            float d0, d1, d2, dq;
            DOT8(d0, a1, b1, C0a, C0b)
            DOT8(d1, a1, b1, C1a, C1b)
            DOT8(d2, a1, b1, C2a, C2b)
            DOT8(dq, a1, b1, a1,  b1)
            const int l = s_lab[i + 1];
            x += (l == 0) ? d0 : ((l == 1) ? d1 : d2);
            ax += d0 + d1 + d2;
            q  += dq;
        }
    }

    double xr  = blk_reduce((double)x,  s_red, 0, tid);
    __syncthreads();
    double axr = blk_reduce((double)ax, s_red, 1, tid);
    __syncthreads();
    double qr  = blk_reduce((double)q,  s_red, 2, tid);

    if (tid == 0) {
        int c0 = 0, c1 = 0;
#pragma unroll
        for (int i = 0; i < RPB; ++i) {
            c0 += (s_lab[i] == 0);
            c1 += (s_lab[i] == 1);
        }
        atomicAdd(&g_cnt0, c0);
        atomicAdd(&g_cnt1, c1);
        atomicAdd(&g_X,  xr);
        atomicAdd(&g_AX, axr);
        atomicAdd(&g_Q,  qr);
        __threadfence();
        int t = atomicAdd(&g_ticket, 1);
        s_last = (t == NBLK - 1);
    }
    __syncthreads();
    if (!s_last) return;

    // ---------------- last block: finalize ----------------
    __threadfence();

    double n0 = 0, n1 = 0, n2 = 0;   // ||c_j||^2
#pragma unroll
    for (int c = tid; c < FEAT_D; c += 256) {
        float v0 = centers[c];
        float v1 = centers[FEAT_D + c];
        float v2 = centers[2 * FEAT_D + c];
        n0 += (double)(v0 * v0);
        n1 += (double)(v1 * v1);
        n2 += (double)(v2 * v2);
    }
    __syncthreads();   // s_red reuse
    double N0 = blk_reduce(n0, s_red, 0, tid);
    __syncthreads();
    double N1 = blk_reduce(n1, s_red, 1, tid);
    __syncthreads();
    double N2 = blk_reduce(n2, s_red, 2, tid);

    if (tid == 0) {
        double X  = atomicAdd(&g_X,  0.0);
        double AX = atomicAdd(&g_AX, 0.0);
        double Q  = atomicAdd(&g_Q,  0.0);
        double C0 = (double)atomicAdd(&g_cnt0, 0);
        double C1 = (double)atomicAdd(&g_cnt1, 0);
        double C2 = (double)B_ROWS - C0 - C1;

        double S_main = Q - 2.0 * X + (C0 * N0 + C1 * N1 + C2 * N2);
        double S_all  = 3.0 * Q - 2.0 * AX + (double)B_ROWS * (N0 + N1 + N2);
        double disto  = S_all - S_main;
        double loss   = S_main * (1.0 + 1.0 / disto) / 2.0 / (double)B_ROWS;
        out[0] = (float)loss;
    }
}

extern "C" void kernel_launch(void* const* d_in, const int* in_sizes, int n_in,
                              void* d_out, int out_size) {
    const float* feat    = (const float*)d_in[0];
    const int*   label32 = (const int*)d_in[1];
    const float* centers = (const float*)d_in[2];
    float*       out     = (float*)d_out;

    init_k<<<1, 32>>>(label32);
    accum_k<<<NBLK, 256>>>(feat, label32, centers, out);
}